// round 2
// baseline (speedup 1.0000x reference)
#include <cuda_runtime.h>
#include <cstdint>

// WindowAttention fused kernel (Swin-style), sm_103a.
// B=8192 windows, N=49 tokens, C=128, H=4 heads, HD=32.
// One CTA per window, 256 threads (8 warps). All GEMMs via mma.sync tf32.
// Pipeline (all in SMEM): x -> qkv -> scores -> softmax(+bias+mask) -> O -> proj -> gmem.

#define NTOK 49
#define MPAD 64          // padded token dim for 16-row mma tiles
#define CDIM 128
#define NH   4
#define HDIM 32
#define LD   132         // row stride (floats) for x/q/k/v/out tiles
#define LDSC 60          // row stride (floats) for score tiles (56 cols used)

// SMEM layout (floats):
//   qs  [64][132]  @ 0      (reused as O buffer in phase 4/5)
//   ks  [64][132]  @ 8448
//   vs  [64][132]  @ 16896
//   sx  region     @ 25344  size 15360  (x tile in phase 1; scores[4][64][60] after)
//   rel [2401] int @ 40704  (pad to 2404)
//   tbl [169*4]    @ 43108
#define OFF_Q   0
#define OFF_K   8448
#define OFF_V   16896
#define OFF_SX  25344
#define OFF_REL 40704
#define OFF_TBL 43108
#define SMEM_FLOATS 43784

__device__ __forceinline__ uint32_t f2tf(float f) {
    uint32_t u;
    asm("cvt.rna.tf32.f32 %0, %1;" : "=r"(u) : "f"(f));
    return u;
}

__device__ __forceinline__ void mma8(float* d, const uint32_t* a, const uint32_t* b) {
    asm volatile(
        "mma.sync.aligned.m16n8k8.row.col.f32.tf32.tf32.f32 "
        "{%0,%1,%2,%3},{%4,%5,%6,%7},{%8,%9},{%0,%1,%2,%3};"
        : "+f"(d[0]), "+f"(d[1]), "+f"(d[2]), "+f"(d[3])
        : "r"(a[0]), "r"(a[1]), "r"(a[2]), "r"(a[3]),
          "r"(b[0]), "r"(b[1]));
}

__global__ __launch_bounds__(256, 1)
void winattn_kernel(const float* __restrict__ x,
                    const float* __restrict__ mask,
                    const float* __restrict__ qkv_w,
                    const float* __restrict__ qkv_b,
                    const float* __restrict__ rel_tbl,
                    const float* __restrict__ proj_w,
                    const float* __restrict__ proj_b,
                    const int*   __restrict__ rel_idx,
                    float*       __restrict__ out)
{
    extern __shared__ float sm[];
    float* qs  = sm + OFF_Q;
    float* ks  = sm + OFF_K;
    float* vs  = sm + OFF_V;
    float* sx  = sm + OFF_SX;                 // x tile, later scores
    int*   rls = (int*)(sm + OFF_REL);
    float* tbl = sm + OFF_TBL;

    const int tid  = threadIdx.x;
    const int lane = tid & 31;
    const int warp = tid >> 5;
    const int g    = lane >> 2;   // groupID (0..7)
    const int tg   = lane & 3;    // threadID_in_group (0..3)
    const int b    = blockIdx.x;

    // ---- Phase 0: stage x window, rel index and bias table ----
    for (int i = tid; i < 2401; i += 256) rls[i] = rel_idx[i];
    for (int i = tid; i < 169 * NH; i += 256) tbl[i] = rel_tbl[i];
    {
        const float* xg = x + (size_t)b * NTOK * CDIM;
        for (int i = tid; i < MPAD * CDIM; i += 256) {
            int r = i >> 7, c = i & 127;
            sx[r * LD + c] = (r < NTOK) ? xg[r * CDIM + c] : 0.0f;
        }
    }
    __syncthreads();

    // ---- Phase 1: qkv = x @ qkv_w + b  (M=64, K=128, N=384) ----
    // warp owns 48 output columns: [warp*48, warp*48+48)
    {
        float acc[4][6][4];
        #pragma unroll
        for (int mt = 0; mt < 4; mt++)
            #pragma unroll
            for (int nt = 0; nt < 6; nt++)
                #pragma unroll
                for (int e = 0; e < 4; e++) acc[mt][nt][e] = 0.0f;

        for (int kk = 0; kk < CDIM; kk += 8) {
            uint32_t Bf[6][2];
            #pragma unroll
            for (int nt = 0; nt < 6; nt++) {
                int col = warp * 48 + nt * 8 + g;
                Bf[nt][0] = f2tf(qkv_w[(kk + tg) * 384 + col]);
                Bf[nt][1] = f2tf(qkv_w[(kk + tg + 4) * 384 + col]);
            }
            #pragma unroll
            for (int mt = 0; mt < 4; mt++) {
                uint32_t Af[4];
                int r = mt * 16 + g;
                Af[0] = f2tf(sx[r * LD + kk + tg]);
                Af[1] = f2tf(sx[(r + 8) * LD + kk + tg]);
                Af[2] = f2tf(sx[r * LD + kk + tg + 4]);
                Af[3] = f2tf(sx[(r + 8) * LD + kk + tg + 4]);
                #pragma unroll
                for (int nt = 0; nt < 6; nt++) mma8(acc[mt][nt], Af, Bf[nt]);
            }
        }

        const float scale = 0.17677669529663687f;  // 32^-0.5
        #pragma unroll
        for (int mt = 0; mt < 4; mt++)
            #pragma unroll
            for (int nt = 0; nt < 6; nt++)
                #pragma unroll
                for (int e = 0; e < 4; e++) {
                    int row = mt * 16 + g + ((e >= 2) ? 8 : 0);
                    int col = warp * 48 + nt * 8 + 2 * tg + (e & 1);
                    float v = acc[mt][nt][e] + qkv_b[col];
                    if (col < 128)       qs[row * LD + col] = v * scale;
                    else if (col < 256)  ks[row * LD + (col - 128)] = v;
                    else                 vs[row * LD + (col - 256)] = v;
                }
    }
    __syncthreads();

    // ---- Phase 2: scores S_h = q_h @ k_h^T  (per head M=64, N=56, K=32) ----
    // warp -> head = warp/2, m-half = warp%2 (m-tiles {2*mh, 2*mh+1})
    {
        const int h  = warp >> 1;
        const int mh = warp & 1;
        float sacc[2][7][4];
        #pragma unroll
        for (int mi = 0; mi < 2; mi++)
            #pragma unroll
            for (int nt = 0; nt < 7; nt++)
                #pragma unroll
                for (int e = 0; e < 4; e++) sacc[mi][nt][e] = 0.0f;

        #pragma unroll
        for (int kk = 0; kk < HDIM; kk += 8) {
            int kb = h * HDIM + kk;
            uint32_t Bf[7][2];
            #pragma unroll
            for (int nt = 0; nt < 7; nt++) {
                int key = nt * 8 + g;
                Bf[nt][0] = f2tf(ks[key * LD + kb + tg]);
                Bf[nt][1] = f2tf(ks[key * LD + kb + tg + 4]);
            }
            #pragma unroll
            for (int mi = 0; mi < 2; mi++) {
                uint32_t Af[4];
                int r = (mh * 2 + mi) * 16 + g;
                Af[0] = f2tf(qs[r * LD + kb + tg]);
                Af[1] = f2tf(qs[(r + 8) * LD + kb + tg]);
                Af[2] = f2tf(qs[r * LD + kb + tg + 4]);
                Af[3] = f2tf(qs[(r + 8) * LD + kb + tg + 4]);
                #pragma unroll
                for (int nt = 0; nt < 7; nt++) mma8(sacc[mi][nt], Af, Bf[nt]);
            }
        }

        float* sh = sx + h * MPAD * LDSC;
        #pragma unroll
        for (int mi = 0; mi < 2; mi++)
            #pragma unroll
            for (int nt = 0; nt < 7; nt++)
                #pragma unroll
                for (int e = 0; e < 4; e++) {
                    int row = (mh * 2 + mi) * 16 + g + ((e >= 2) ? 8 : 0);
                    int col = nt * 8 + 2 * tg + (e & 1);
                    sh[row * LDSC + col] = sacc[mi][nt][e];
                }
    }
    __syncthreads();

    // ---- Phase 3: softmax(S + rel_bias + mask) along keys, per (head,row) ----
    if (tid < NH * NTOK) {
        const int h   = tid / NTOK;
        const int row = tid % NTOK;
        float* srow = sx + h * MPAD * LDSC + row * LDSC;
        const float* mrow = mask + ((size_t)b * NTOK + row) * NTOK;
        const int* rrow = rls + row * NTOK;

        float mx = -1e30f;
        for (int j = 0; j < NTOK; j++) {
            float v = srow[j] + tbl[rrow[j] * NH + h] + mrow[j];
            srow[j] = v;
            mx = fmaxf(mx, v);
        }
        float sum = 0.0f;
        for (int j = 0; j < NTOK; j++) {
            float e = expf(srow[j] - mx);
            srow[j] = e;
            sum += e;
        }
        float inv = 1.0f / sum;
        for (int j = 0; j < NTOK; j++) srow[j] *= inv;
        // zero padded key columns (49..55) so the P@V GEMM ignores them
        for (int j = NTOK; j < 56; j++) srow[j] = 0.0f;
    }
    __syncthreads();

    // ---- Phase 4: O_h = P_h @ v_h  (per head M=64, N=32, K=56) -> qs buffer ----
    {
        const int h  = warp >> 1;
        const int mh = warp & 1;
        float* sh = sx + h * MPAD * LDSC;
        float oacc[2][4][4];
        #pragma unroll
        for (int mi = 0; mi < 2; mi++)
            #pragma unroll
            for (int nt = 0; nt < 4; nt++)
                #pragma unroll
                for (int e = 0; e < 4; e++) oacc[mi][nt][e] = 0.0f;

        #pragma unroll
        for (int kk = 0; kk < 56; kk += 8) {
            uint32_t Bf[4][2];
            #pragma unroll
            for (int nt = 0; nt < 4; nt++) {
                int vc = h * HDIM + nt * 8 + g;
                Bf[nt][0] = f2tf(vs[(kk + tg) * LD + vc]);
                Bf[nt][1] = f2tf(vs[(kk + tg + 4) * LD + vc]);
            }
            #pragma unroll
            for (int mi = 0; mi < 2; mi++) {
                uint32_t Af[4];
                int r = (mh * 2 + mi) * 16 + g;
                Af[0] = f2tf(sh[r * LDSC + kk + tg]);
                Af[1] = f2tf(sh[(r + 8) * LDSC + kk + tg]);
                Af[2] = f2tf(sh[r * LDSC + kk + tg + 4]);
                Af[3] = f2tf(sh[(r + 8) * LDSC + kk + tg + 4]);
                #pragma unroll
                for (int nt = 0; nt < 4; nt++) mma8(oacc[mi][nt], Af, Bf[nt]);
            }
        }

        // store O into qs (q is dead after phase 2; syncthreads above fence it)
        #pragma unroll
        for (int mi = 0; mi < 2; mi++)
            #pragma unroll
            for (int nt = 0; nt < 4; nt++)
                #pragma unroll
                for (int e = 0; e < 4; e++) {
                    int row = (mh * 2 + mi) * 16 + g + ((e >= 2) ? 8 : 0);
                    int col = h * HDIM + nt * 8 + 2 * tg + (e & 1);
                    qs[row * LD + col] = oacc[mi][nt][e];
                }
    }
    __syncthreads();

    // ---- Phase 5: result = O @ proj_w + proj_b  (M=64, K=128, N=128) ----
    // warp owns 16 output columns
    {
        float pacc[4][2][4];
        #pragma unroll
        for (int mt = 0; mt < 4; mt++)
            #pragma unroll
            for (int nt = 0; nt < 2; nt++)
                #pragma unroll
                for (int e = 0; e < 4; e++) pacc[mt][nt][e] = 0.0f;

        for (int kk = 0; kk < CDIM; kk += 8) {
            uint32_t Bf[2][2];
            #pragma unroll
            for (int nt = 0; nt < 2; nt++) {
                int col = warp * 16 + nt * 8 + g;
                Bf[nt][0] = f2tf(proj_w[(kk + tg) * CDIM + col]);
                Bf[nt][1] = f2tf(proj_w[(kk + tg + 4) * CDIM + col]);
            }
            #pragma unroll
            for (int mt = 0; mt < 4; mt++) {
                uint32_t Af[4];
                int r = mt * 16 + g;
                Af[0] = f2tf(qs[r * LD + kk + tg]);
                Af[1] = f2tf(qs[(r + 8) * LD + kk + tg]);
                Af[2] = f2tf(qs[r * LD + kk + tg + 4]);
                Af[3] = f2tf(qs[(r + 8) * LD + kk + tg + 4]);
                #pragma unroll
                for (int nt = 0; nt < 2; nt++) mma8(pacc[mt][nt], Af, Bf[nt]);
            }
        }

        float* og = out + (size_t)b * NTOK * CDIM;
        #pragma unroll
        for (int mt = 0; mt < 4; mt++)
            #pragma unroll
            for (int nt = 0; nt < 2; nt++)
                #pragma unroll
                for (int e = 0; e < 4; e++) {
                    int row = mt * 16 + g + ((e >= 2) ? 8 : 0);
                    int col = warp * 16 + nt * 8 + 2 * tg + (e & 1);
                    if (row < NTOK)
                        og[row * CDIM + col] = pacc[mt][nt][e] + proj_b[col];
                }
    }
}

extern "C" void kernel_launch(void* const* d_in, const int* in_sizes, int n_in,
                              void* d_out, int out_size) {
    const float* x      = (const float*)d_in[0];
    const float* mask   = (const float*)d_in[1];
    const float* qkv_w  = (const float*)d_in[2];
    const float* qkv_b  = (const float*)d_in[3];
    const float* rtbl   = (const float*)d_in[4];
    const float* proj_w = (const float*)d_in[5];
    const float* proj_b = (const float*)d_in[6];
    const int*   ridx   = (const int*)d_in[7];
    float* out = (float*)d_out;

    const int B = in_sizes[0] / (NTOK * CDIM);
    const int smem_bytes = SMEM_FLOATS * sizeof(float);
    cudaFuncSetAttribute(winattn_kernel,
                         cudaFuncAttributeMaxDynamicSharedMemorySize, smem_bytes);
    winattn_kernel<<<B, 256, smem_bytes>>>(x, mask, qkv_w, qkv_b, rtbl,
                                           proj_w, proj_b, ridx, out);
}

// round 3
// speedup vs baseline: 1.1674x; 1.1674x over previous
#include <cuda_runtime.h>
#include <cstdint>

// WindowAttention fused v2 (sm_103a).
// B=8192 windows, N=49, C=128, H=4, HD=32.
// 512 threads (16 warps), 1 window/CTA. mma.sync m16n8k8 tf32 everywhere.
// Weights pre-converted to tf32 packed-pair layout by a prep kernel so every
// B-fragment is a single coalesced LDG.64 (prefetched). All smem tiles are
// tf32 packed pairs with conflict-free odd strides -> A/B fragments = LDS.64.
// Softmax entirely in registers (shfl reductions).

#define NTOK 49
#define CDIM 128
#define NH   4

// packed-pair geometry:
//  row-major tiles (x,q,k,O): pair idx = r*66 + kc*4 + tg   (stride 66 uint2)
//  col-major tiles (v) / P:   pair idx = c*30 + kc*4 + tg   (stride 30 uint2)
#define RSTRIDE 66
#define CSTRIDE 30

// smem offsets in u32 words
#define XP_OFF   0          // 64*132 = 8448 u32  (x; later P rows 0..140)
#define QP_OFF   8448       // 8448 u32           (q; later P rows 141..255)
#define KP_OFF   16896      // 8448 u32           (k; later O)
#define VP_OFF   25344      // 128*60 = 7680 u32  (v, col-major, 7 kc)
#define TBL_OFF  33024      // 676 floats
#define SMEM_U32 33700      // 134800 bytes

__device__ uint2 g_wq[16 * 384 * 4];   // qkv_w tf32 pairs: [kc][col][tg]
__device__ uint2 g_wp[16 * 128 * 4];   // proj_w tf32 pairs: [kc][col][tg]

__device__ __forceinline__ uint32_t f2tf(float f) {
    uint32_t u;
    asm("cvt.rna.tf32.f32 %0, %1;" : "=r"(u) : "f"(f));
    return u;
}

__device__ __forceinline__ void mma8(float* d,
                                     uint32_t a0, uint32_t a1, uint32_t a2, uint32_t a3,
                                     uint32_t b0, uint32_t b1) {
    asm volatile(
        "mma.sync.aligned.m16n8k8.row.col.f32.tf32.tf32.f32 "
        "{%0,%1,%2,%3},{%4,%5,%6,%7},{%8,%9},{%0,%1,%2,%3};"
        : "+f"(d[0]), "+f"(d[1]), "+f"(d[2]), "+f"(d[3])
        : "r"(a0), "r"(a1), "r"(a2), "r"(a3), "r"(b0), "r"(b1));
}

// ---------------- prep: convert weights to tf32 packed pairs ----------------
__global__ void prep_kernel(const float* __restrict__ qkv_w,
                            const float* __restrict__ proj_w) {
    int i = blockIdx.x * blockDim.x + threadIdx.x;
    if (i < 16 * 384 * 4) {
        int kc  = i / 1536;
        int rem = i - kc * 1536;
        int col = rem >> 2;
        int tg  = rem & 3;
        uint2 p;
        p.x = f2tf(qkv_w[(kc * 8 + tg)     * 384 + col]);
        p.y = f2tf(qkv_w[(kc * 8 + tg + 4) * 384 + col]);
        g_wq[i] = p;
    } else {
        int j = i - 16 * 384 * 4;
        if (j < 16 * 128 * 4) {
            int kc  = j >> 9;
            int rem = j & 511;
            int col = rem >> 2;
            int tg  = rem & 3;
            uint2 p;
            p.x = f2tf(proj_w[(kc * 8 + tg)     * 128 + col]);
            p.y = f2tf(proj_w[(kc * 8 + tg + 4) * 128 + col]);
            g_wp[j] = p;
        }
    }
}

// row-major pair store index (u32 units)
__device__ __forceinline__ int rm_idx(int r, int c) {
    return ((r * RSTRIDE + ((c >> 3) << 2) + (c & 3)) << 1) + ((c >> 2) & 1);
}
// col-major pair store index (u32 units) — for v / P
__device__ __forceinline__ int cm_idx(int c, int r) {
    return ((c * CSTRIDE + ((r >> 3) << 2) + (r & 3)) << 1) + ((r >> 2) & 1);
}

__global__ __launch_bounds__(512, 1)
void winattn2_kernel(const float* __restrict__ x,
                     const float* __restrict__ mask,
                     const float* __restrict__ qkv_b,
                     const float* __restrict__ rel_tbl,
                     const float* __restrict__ proj_b,
                     float*       __restrict__ out)
{
    extern __shared__ uint32_t sm[];
    uint32_t* const xp  = sm + XP_OFF;
    uint32_t* const qp  = sm + QP_OFF;
    uint32_t* const kp  = sm + KP_OFF;
    uint32_t* const vp  = sm + VP_OFF;
    float*    const tbl = (float*)(sm + TBL_OFF);
    uint32_t* const pp  = sm + XP_OFF;    // P overlays x+q (15360 u32 < 16896)
    uint32_t* const op  = sm + KP_OFF;    // O overlays k

    const uint2* const xp2 = (const uint2*)xp;
    const uint2* const qp2 = (const uint2*)qp;
    const uint2* const kp2 = (const uint2*)kp;
    const uint2* const vp2 = (const uint2*)vp;
    const uint2* const pp2 = (const uint2*)pp;
    const uint2* const op2 = (const uint2*)op;

    const int tid  = threadIdx.x;
    const int lane = tid & 31;
    const int warp = tid >> 5;     // 0..15
    const int g    = lane >> 2;    // 0..7
    const int tg   = lane & 3;     // 0..3
    const int b    = blockIdx.x;

    // ---- Phase 0: stage x (tf32 pairs) + bias table ----
    {
        const float* xg = x + (size_t)b * NTOK * CDIM;
        for (int i = tid; i < 64 * 128; i += 512) {
            int r = i >> 7, c = i & 127;
            float v = (r < NTOK) ? __ldg(xg + r * CDIM + c) : 0.0f;
            xp[rm_idx(r, c)] = f2tf(v);
        }
        for (int i = tid; i < 169 * NH; i += 512) tbl[i] = __ldg(rel_tbl + i);
    }
    __syncthreads();

    // ---- Phase 1: qkv = x @ qkv_w + b  (M=64, N=384, K=128) ----
    // warp owns 24 cols. B-fragments: single LDG.64 from g_wq, prefetched.
    {
        const int colbase = warp * 24;
        float acc[4][3][4];
        #pragma unroll
        for (int mt = 0; mt < 4; mt++)
            #pragma unroll
            for (int nt = 0; nt < 3; nt++)
                #pragma unroll
                for (int e = 0; e < 4; e++) acc[mt][nt][e] = 0.0f;

        uint2 Bc[3], Bn[3];
        {
            const uint2* w0 = g_wq + (colbase + g) * 4 + tg;
            #pragma unroll
            for (int nt = 0; nt < 3; nt++) Bc[nt] = __ldg(w0 + nt * 32);
        }
        for (int kc = 0; kc < 16; kc++) {
            if (kc < 15) {
                const uint2* wn = g_wq + (kc + 1) * 1536 + (colbase + g) * 4 + tg;
                #pragma unroll
                for (int nt = 0; nt < 3; nt++) Bn[nt] = __ldg(wn + nt * 32);
            }
            #pragma unroll
            for (int mt = 0; mt < 4; mt++) {
                int r = mt * 16 + g;
                uint2 a0 = xp2[r * RSTRIDE + kc * 4 + tg];
                uint2 a1 = xp2[(r + 8) * RSTRIDE + kc * 4 + tg];
                #pragma unroll
                for (int nt = 0; nt < 3; nt++)
                    mma8(acc[mt][nt], a0.x, a1.x, a0.y, a1.y, Bc[nt].x, Bc[nt].y);
            }
            #pragma unroll
            for (int nt = 0; nt < 3; nt++) Bc[nt] = Bn[nt];
        }

        const float scale = 0.17677669529663687f;  // 32^-0.5
        #pragma unroll
        for (int mt = 0; mt < 4; mt++)
            #pragma unroll
            for (int nt = 0; nt < 3; nt++)
                #pragma unroll
                for (int e = 0; e < 4; e++) {
                    int row = mt * 16 + g + ((e >= 2) ? 8 : 0);
                    int col = colbase + nt * 8 + 2 * tg + (e & 1);
                    float v = acc[mt][nt][e] + __ldg(qkv_b + col);
                    if (col < 128) {
                        qp[rm_idx(row, col)] = f2tf(v * scale);
                    } else if (col < 256) {
                        kp[rm_idx(row, col - 128)] = f2tf(v);
                    } else {
                        if (row < 56) vp[cm_idx(col - 256, row)] = f2tf(v);
                    }
                }
    }
    __syncthreads();

    // ---- Phase 2: S = q @ k^T  per (head, 16-row slice). warp=(h, mh) ----
    const int h    = warp >> 2;   // 0..3
    const int mh   = warp & 3;    // 0..3
    const int row0 = mh * 16;
    float sacc[7][4];
    #pragma unroll
    for (int nt = 0; nt < 7; nt++)
        #pragma unroll
        for (int e = 0; e < 4; e++) sacc[nt][e] = 0.0f;

    #pragma unroll
    for (int kcl = 0; kcl < 4; kcl++) {
        int kc = h * 4 + kcl;
        uint2 a0 = qp2[(row0 + g) * RSTRIDE + kc * 4 + tg];
        uint2 a1 = qp2[(row0 + g + 8) * RSTRIDE + kc * 4 + tg];
        #pragma unroll
        for (int nt = 0; nt < 7; nt++) {
            uint2 bk = kp2[(nt * 8 + g) * RSTRIDE + kc * 4 + tg];
            mma8(sacc[nt], a0.x, a1.x, a0.y, a1.y, bk.x, bk.y);
        }
    }
    __syncthreads();   // all q/k reads done before P overwrites those regions

    // ---- Phase 3: softmax(S + bias + mask) in registers; write P pairs ----
    {
        const float* mbase = mask + (size_t)b * NTOK * NTOK;
        #pragma unroll
        for (int half = 0; half < 2; half++) {
            int rr = row0 + g + half * 8;
            bool rv = rr < NTOK;
            int rq = rv ? ((rr * 9363) >> 16) : 0;   // rr/7
            int rm = rv ? (rr - rq * 7) : 0;
            float vals[14];
            float mx = -1e30f;
            #pragma unroll
            for (int nt = 0; nt < 7; nt++)
                #pragma unroll
                for (int e = 0; e < 2; e++) {
                    int j = nt * 8 + 2 * tg + e;
                    float s = sacc[nt][half * 2 + e];
                    if (j < NTOK) {
                        if (rv) {
                            int cq = (j * 9363) >> 16;
                            int cm = j - cq * 7;
                            int rel = (rq - cq + 6) * 13 + (rm - cm + 6);
                            s += tbl[rel * NH + h] + __ldg(mbase + rr * NTOK + j);
                        }
                    } else {
                        s = -1e30f;   // padded keys -> P = 0
                    }
                    vals[nt * 2 + e] = s;
                    mx = fmaxf(mx, s);
                }
            mx = fmaxf(mx, __shfl_xor_sync(0xffffffffu, mx, 1));
            mx = fmaxf(mx, __shfl_xor_sync(0xffffffffu, mx, 2));
            float sum = 0.0f;
            #pragma unroll
            for (int i = 0; i < 14; i++) {
                vals[i] = __expf(vals[i] - mx);
                sum += vals[i];
            }
            sum += __shfl_xor_sync(0xffffffffu, sum, 1);
            sum += __shfl_xor_sync(0xffffffffu, sum, 2);
            float inv = 1.0f / sum;
            int pr = h * 64 + rr;
            #pragma unroll
            for (int nt = 0; nt < 7; nt++)
                #pragma unroll
                for (int e = 0; e < 2; e++) {
                    int j = nt * 8 + 2 * tg + e;
                    pp[cm_idx(pr, j)] = f2tf(vals[nt * 2 + e] * inv);
                }
        }
    }
    __syncwarp();   // warp reads only its own 16 P rows (written by itself)

    // ---- Phase 4: O = P @ v  per warp (M=16 rows, N=32 head cols, K=56) ----
    {
        float oacc[4][4];
        #pragma unroll
        for (int nt = 0; nt < 4; nt++)
            #pragma unroll
            for (int e = 0; e < 4; e++) oacc[nt][e] = 0.0f;

        #pragma unroll
        for (int kc = 0; kc < 7; kc++) {
            uint2 a0 = pp2[(h * 64 + row0 + g) * CSTRIDE + kc * 4 + tg];
            uint2 a1 = pp2[(h * 64 + row0 + g + 8) * CSTRIDE + kc * 4 + tg];
            #pragma unroll
            for (int nt = 0; nt < 4; nt++) {
                uint2 bv = vp2[(h * 32 + nt * 8 + g) * CSTRIDE + kc * 4 + tg];
                mma8(oacc[nt], a0.x, a1.x, a0.y, a1.y, bv.x, bv.y);
            }
        }
        #pragma unroll
        for (int nt = 0; nt < 4; nt++)
            #pragma unroll
            for (int e = 0; e < 4; e++) {
                int row = row0 + g + ((e >= 2) ? 8 : 0);
                int col = h * 32 + nt * 8 + 2 * tg + (e & 1);
                op[rm_idx(row, col)] = f2tf(oacc[nt][e]);
            }
    }
    __syncthreads();

    // ---- Phase 5: out = O @ proj_w + proj_b  (M=64, N=128, K=128) ----
    {
        const int col5 = warp * 8 + g;   // warp owns 8 cols
        float pacc[4][4];
        #pragma unroll
        for (int mt = 0; mt < 4; mt++)
            #pragma unroll
            for (int e = 0; e < 4; e++) pacc[mt][e] = 0.0f;

        uint2 Pc = __ldg(g_wp + col5 * 4 + tg), Pn;
        for (int kc = 0; kc < 16; kc++) {
            if (kc < 15) Pn = __ldg(g_wp + (kc + 1) * 512 + col5 * 4 + tg);
            #pragma unroll
            for (int mt = 0; mt < 4; mt++) {
                int r = mt * 16 + g;
                uint2 a0 = op2[r * RSTRIDE + kc * 4 + tg];
                uint2 a1 = op2[(r + 8) * RSTRIDE + kc * 4 + tg];
                mma8(pacc[mt], a0.x, a1.x, a0.y, a1.y, Pc.x, Pc.y);
            }
            Pc = Pn;
        }

        float* og = out + (size_t)b * NTOK * CDIM;
        const int cc = warp * 8 + 2 * tg;
        const float pb0 = __ldg(proj_b + cc);
        const float pb1 = __ldg(proj_b + cc + 1);
        #pragma unroll
        for (int mt = 0; mt < 4; mt++) {
            int r = mt * 16 + g;
            if (r < NTOK) {
                float2 v = make_float2(pacc[mt][0] + pb0, pacc[mt][1] + pb1);
                *(float2*)(og + r * CDIM + cc) = v;
            }
            if (r + 8 < NTOK) {
                float2 v = make_float2(pacc[mt][2] + pb0, pacc[mt][3] + pb1);
                *(float2*)(og + (r + 8) * CDIM + cc) = v;
            }
        }
    }
}

extern "C" void kernel_launch(void* const* d_in, const int* in_sizes, int n_in,
                              void* d_out, int out_size) {
    const float* x      = (const float*)d_in[0];
    const float* mask   = (const float*)d_in[1];
    const float* qkv_w  = (const float*)d_in[2];
    const float* qkv_b  = (const float*)d_in[3];
    const float* rtbl   = (const float*)d_in[4];
    const float* proj_w = (const float*)d_in[5];
    const float* proj_b = (const float*)d_in[6];
    float* out = (float*)d_out;

    const int B = in_sizes[0] / (NTOK * CDIM);
    prep_kernel<<<64, 512>>>(qkv_w, proj_w);

    const int smem_bytes = SMEM_U32 * sizeof(uint32_t);
    static bool attr_set = false;
    cudaFuncSetAttribute(winattn2_kernel,
                         cudaFuncAttributeMaxDynamicSharedMemorySize, smem_bytes);
    (void)attr_set;
    winattn2_kernel<<<B, 512, smem_bytes>>>(x, mask, qkv_b, rtbl, proj_b, out);
}

// round 8
// speedup vs baseline: 2.1426x; 1.8354x over previous
#include <cuda_runtime.h>
#include <cstdint>

// WindowAttention fused v3.1 (sm_103a).
// 256 threads (8 warps), 1 window/CTA, 2 CTAs/SM (smem 104.9KB, regs<=128).
// Warp w: mi=w&3 (16-row slice), hp=w>>2; owns heads {hp, hp+2}.
// q stays in registers (shfl transpose acc->A frag). Conflict-free pair strides.
// v3.1: phase-3 mask loads hoisted (head-independent, loaded once per row-half,
// batched before the softmax dependency chain).

#define NTOK 49
#define CDIM 128

#define RS 68   // row-major pair stride (x / k / O)  : 68 mod 16 == 4 -> CF
#define VS 36   // v col-major pair stride            : 36 mod 16 == 4 -> CF
#define PS 28   // P row pair stride                  : 28 mod 16 == 12 -> CF

// u32-word offsets
#define X_OFF   0        // x: 64*68 pairs = 8704 u32 ; P(14336) & O(8704) overlay
#define K_OFF   8704     // k: 56*68 pairs = 7616 u32
#define V_OFF   16320    // v: 128*36 pairs = 9216 u32
#define TBL_OFF 25536    // 676 floats
#define SMEM_U32 26216   // 104864 bytes

__device__ uint2 g_wq[16 * 384 * 4];   // qkv_w tf32 pairs [kc][col][tg]
__device__ uint2 g_wp[16 * 128 * 4];   // proj_w tf32 pairs [kc][col][tg]

__device__ __forceinline__ uint32_t f2tf(float f) {
    uint32_t u;
    asm("cvt.rna.tf32.f32 %0, %1;" : "=r"(u) : "f"(f));
    return u;
}

__device__ __forceinline__ void mma8(float* d,
                                     uint32_t a0, uint32_t a1, uint32_t a2, uint32_t a3,
                                     uint32_t b0, uint32_t b1) {
    asm volatile(
        "mma.sync.aligned.m16n8k8.row.col.f32.tf32.tf32.f32 "
        "{%0,%1,%2,%3},{%4,%5,%6,%7},{%8,%9},{%0,%1,%2,%3};"
        : "+f"(d[0]), "+f"(d[1]), "+f"(d[2]), "+f"(d[3])
        : "r"(a0), "r"(a1), "r"(a2), "r"(a3), "r"(b0), "r"(b1));
}

// scalar u32 element indices into pair layouts
__device__ __forceinline__ int rm(int r, int c) {
    return ((r * RS + ((c >> 3) << 2) + (c & 3)) << 1) + ((c >> 2) & 1);
}
__device__ __forceinline__ int vm(int c, int r) {
    return ((c * VS + ((r >> 3) << 2) + (r & 3)) << 1) + ((r >> 2) & 1);
}
__device__ __forceinline__ int pm(int pr, int j) {
    return ((pr * PS + ((j >> 3) << 2) + (j & 3)) << 1) + ((j >> 2) & 1);
}

// ---------------- prep: weights -> tf32 packed pairs ----------------
__global__ void prep_kernel(const float* __restrict__ qkv_w,
                            const float* __restrict__ proj_w) {
    int i = blockIdx.x * blockDim.x + threadIdx.x;
    if (i < 16 * 384 * 4) {
        int kc = i / 1536, rem = i - kc * 1536;
        int col = rem >> 2, tg = rem & 3;
        uint2 p;
        p.x = f2tf(qkv_w[(kc * 8 + tg)     * 384 + col]);
        p.y = f2tf(qkv_w[(kc * 8 + tg + 4) * 384 + col]);
        g_wq[i] = p;
    } else {
        int j = i - 16 * 384 * 4;
        if (j < 16 * 128 * 4) {
            int kc = j >> 9, rem = j & 511;
            int col = rem >> 2, tg = rem & 3;
            uint2 p;
            p.x = f2tf(proj_w[(kc * 8 + tg)     * 128 + col]);
            p.y = f2tf(proj_w[(kc * 8 + tg + 4) * 128 + col]);
            g_wp[j] = p;
        }
    }
}

// 16-row x 64-col GEMM slice: acc[8][4] += A(16xK) * W(Kx64), K = 16 kc chunks.
// A from packed-pair smem (stride RS); W from global pair layout (double-buffered).
__device__ __forceinline__ void gemm16(const uint2* __restrict__ ap2,
                                       const uint2* __restrict__ w,
                                       int wstride,          // uint2 per kc
                                       int mi, int g, int tg,
                                       const int* colW,      // 8 col bases
                                       float acc[8][4]) {
    #pragma unroll
    for (int nt = 0; nt < 8; nt++)
        #pragma unroll
        for (int e = 0; e < 4; e++) acc[nt][e] = 0.0f;

    uint2 Bc[8], Bn[8];
    #pragma unroll
    for (int nt = 0; nt < 8; nt++) Bc[nt] = __ldg(w + (colW[nt] + g) * 4 + tg);

    #pragma unroll
    for (int kc = 0; kc < 16; kc++) {
        if (kc < 15) {
            const uint2* wn = w + (kc + 1) * wstride;
            #pragma unroll
            for (int nt = 0; nt < 8; nt++) Bn[nt] = __ldg(wn + (colW[nt] + g) * 4 + tg);
        }
        uint2 a0 = ap2[(16 * mi + g) * RS + kc * 4 + tg];
        uint2 a1 = ap2[(16 * mi + 8 + g) * RS + kc * 4 + tg];
        #pragma unroll
        for (int nt = 0; nt < 8; nt++)
            mma8(acc[nt], a0.x, a1.x, a0.y, a1.y, Bc[nt].x, Bc[nt].y);
        #pragma unroll
        for (int nt = 0; nt < 8; nt++) Bc[nt] = Bn[nt];
    }
}

__global__ __launch_bounds__(256, 2)
void winattn3_kernel(const float* __restrict__ x,
                     const float* __restrict__ mask,
                     const float* __restrict__ qkv_b,
                     const float* __restrict__ rel_tbl,
                     const float* __restrict__ proj_b,
                     float*       __restrict__ out)
{
    extern __shared__ uint32_t sm[];
    uint32_t* const xp  = sm + X_OFF;
    uint32_t* const kp  = sm + K_OFF;
    uint32_t* const vp  = sm + V_OFF;
    float*    const tbl = (float*)(sm + TBL_OFF);
    uint32_t* const pp  = sm + X_OFF;   // P overlays x + k (14336 <= 16320)
    uint32_t* const op  = sm + X_OFF;   // O overlays P region after sync

    const uint2* const xp2 = (const uint2*)xp;
    const uint2* const kp2 = (const uint2*)kp;
    const uint2* const vp2 = (const uint2*)vp;
    const uint2* const pp2 = (const uint2*)pp;
    const uint2* const op2 = (const uint2*)op;

    const int tid  = threadIdx.x;
    const int lane = tid & 31;
    const int wid  = tid >> 5;     // 0..7
    const int mi   = wid & 3;      // 16-row slice
    const int hp   = wid >> 2;     // 0..1
    const int g    = lane >> 2;
    const int tg   = lane & 3;
    const int b    = blockIdx.x;
    const int h0   = hp, h1 = hp + 2;

    // ---- Phase 0: stage x + bias table ----
    {
        const float* xg = x + (size_t)b * NTOK * CDIM;
        for (int i = tid; i < 64 * 128; i += 256) {
            int r = i >> 7, c = i & 127;
            float v = (r < NTOK) ? __ldg(xg + r * CDIM + c) : 0.0f;
            xp[rm(r, c)] = f2tf(v);
        }
        for (int i = tid; i < 169 * 4; i += 256) tbl[i] = __ldg(rel_tbl + i);
    }
    __syncthreads();

    uint32_t qt[8][4];   // q tf32 fragments for heads h0 (nt 0-3), h1 (nt 4-7)

    // ---- Phase 1: qkv in three passes (K, V, Q), each M=16 x N=64 per warp ----
    {
        int colK[8], colV[8], colQ[8];
        #pragma unroll
        for (int nt = 0; nt < 8; nt++) {
            int hh = (nt < 4) ? h0 : h1;
            int base = 32 * hh + 8 * (nt & 3);
            colQ[nt] = base;
            colK[nt] = 128 + base;
            colV[nt] = 256 + base;
        }
        float acc[8][4];

        // K pass
        gemm16(xp2, g_wq, 1536, mi, g, tg, colK, acc);
        #pragma unroll
        for (int nt = 0; nt < 8; nt++)
            #pragma unroll
            for (int e = 0; e < 4; e++) {
                int row = 16 * mi + g + ((e >= 2) ? 8 : 0);
                int cw  = colK[nt] + 2 * tg + (e & 1);
                float v = acc[nt][e] + __ldg(qkv_b + cw);
                if (row < 56) kp[rm(row, cw - 128)] = f2tf(v);
            }

        // V pass
        gemm16(xp2, g_wq, 1536, mi, g, tg, colV, acc);
        #pragma unroll
        for (int nt = 0; nt < 8; nt++)
            #pragma unroll
            for (int e = 0; e < 4; e++) {
                int row = 16 * mi + g + ((e >= 2) ? 8 : 0);
                int cw  = colV[nt] + 2 * tg + (e & 1);
                float v = acc[nt][e] + __ldg(qkv_b + cw);
                if (row < 56) vp[vm(cw - 256, row)] = f2tf(v);
            }

        // Q pass -> registers only
        const float scale = 0.17677669529663687f;  // 32^-0.5
        gemm16(xp2, g_wq, 1536, mi, g, tg, colQ, acc);
        #pragma unroll
        for (int nt = 0; nt < 8; nt++)
            #pragma unroll
            for (int e = 0; e < 4; e++) {
                int cw = colQ[nt] + 2 * tg + (e & 1);
                qt[nt][e] = f2tf((acc[nt][e] + __ldg(qkv_b + cw)) * scale);
            }
    }
    __syncthreads();

    // ---- Phase 2: S = q k^T for both heads (q via shfl transpose) ----
    float sacc[2][7][4];
    {
        const int src0 = (lane & ~3) | (tg >> 1);
        const int src1 = src0 + 2;
        const bool hi  = (tg & 1);
        #pragma unroll
        for (int hh = 0; hh < 2; hh++) {
            const int h = hh ? h1 : h0;
            #pragma unroll
            for (int nt = 0; nt < 7; nt++)
                #pragma unroll
                for (int e = 0; e < 4; e++) sacc[hh][nt][e] = 0.0f;

            #pragma unroll
            for (int kcl = 0; kcl < 4; kcl++) {
                const int q = hh * 4 + kcl;
                uint32_t u00 = __shfl_sync(0xffffffffu, qt[q][0], src0);
                uint32_t u01 = __shfl_sync(0xffffffffu, qt[q][1], src0);
                uint32_t u10 = __shfl_sync(0xffffffffu, qt[q][2], src0);
                uint32_t u11 = __shfl_sync(0xffffffffu, qt[q][3], src0);
                uint32_t v00 = __shfl_sync(0xffffffffu, qt[q][0], src1);
                uint32_t v01 = __shfl_sync(0xffffffffu, qt[q][1], src1);
                uint32_t v10 = __shfl_sync(0xffffffffu, qt[q][2], src1);
                uint32_t v11 = __shfl_sync(0xffffffffu, qt[q][3], src1);
                uint32_t a0 = hi ? u01 : u00;
                uint32_t a1 = hi ? u11 : u10;
                uint32_t a2 = hi ? v01 : v00;
                uint32_t a3 = hi ? v11 : v10;
                #pragma unroll
                for (int nt = 0; nt < 7; nt++) {
                    uint2 bk = kp2[(nt * 8 + g) * RS + (h * 4 + kcl) * 4 + tg];
                    mma8(sacc[hh][nt], a0, a1, a2, a3, bk.x, bk.y);
                }
            }
        }
    }
    __syncthreads();   // all k reads done; P may overlay x+k

    // ---- Phase 3: softmax (registers) -> P ----
    // Mask is head-independent: load each row-half's 14 mask values ONCE
    // (batched, MLP=14) and reuse across both heads.
    {
        const float* mbase = mask + (size_t)b * NTOK * NTOK;
        #pragma unroll
        for (int half = 0; half < 2; half++) {
            int rr = 16 * mi + g + 8 * half;
            bool rv = rr < NTOK;
            int rq = rv ? ((rr * 9363) >> 16) : 0;   // rr/7
            int rmm = rv ? (rr - rq * 7) : 0;

            float mv[14];
            #pragma unroll
            for (int nt = 0; nt < 7; nt++)
                #pragma unroll
                for (int e = 0; e < 2; e++) {
                    int j = nt * 8 + 2 * tg + e;
                    mv[nt * 2 + e] = (rv && j < NTOK)
                        ? __ldg(mbase + rr * NTOK + j) : 0.0f;
                }

            #pragma unroll
            for (int hh = 0; hh < 2; hh++) {
                const int h = hh ? h1 : h0;
                float vals[14];
                float mx = -1e30f;
                #pragma unroll
                for (int nt = 0; nt < 7; nt++)
                    #pragma unroll
                    for (int e = 0; e < 2; e++) {
                        int j = nt * 8 + 2 * tg + e;
                        float s = sacc[hh][nt][half * 2 + e];
                        if (j < NTOK) {
                            if (rv) {
                                int cq = (j * 9363) >> 16;
                                int cm = j - cq * 7;
                                int rel = (rq - cq + 6) * 13 + (rmm - cm + 6);
                                s += tbl[rel * 4 + h] + mv[nt * 2 + e];
                            }
                        } else {
                            s = -1e30f;
                        }
                        vals[nt * 2 + e] = s;
                        mx = fmaxf(mx, s);
                    }
                mx = fmaxf(mx, __shfl_xor_sync(0xffffffffu, mx, 1));
                mx = fmaxf(mx, __shfl_xor_sync(0xffffffffu, mx, 2));
                float sum = 0.0f;
                #pragma unroll
                for (int i = 0; i < 14; i++) {
                    vals[i] = __expf(vals[i] - mx);
                    sum += vals[i];
                }
                sum += __shfl_xor_sync(0xffffffffu, sum, 1);
                sum += __shfl_xor_sync(0xffffffffu, sum, 2);
                float inv = 1.0f / sum;
                int pr = h * 64 + rr;
                #pragma unroll
                for (int nt = 0; nt < 7; nt++)
                    #pragma unroll
                    for (int e = 0; e < 2; e++) {
                        int j = nt * 8 + 2 * tg + e;
                        pp[pm(pr, j)] = f2tf(vals[nt * 2 + e] * inv);
                    }
            }
        }
    }
    __syncwarp();   // each warp reads only its own P rows in phase 4

    // ---- Phase 4: O = P @ v for both heads (acc in regs) ----
    float oacc[2][4][4];
    {
        #pragma unroll
        for (int hh = 0; hh < 2; hh++) {
            const int h = hh ? h1 : h0;
            #pragma unroll
            for (int nt = 0; nt < 4; nt++)
                #pragma unroll
                for (int e = 0; e < 4; e++) oacc[hh][nt][e] = 0.0f;
            #pragma unroll
            for (int kc = 0; kc < 7; kc++) {
                uint2 pa = pp2[(h * 64 + 16 * mi + g) * PS + kc * 4 + tg];
                uint2 pb = pp2[(h * 64 + 16 * mi + 8 + g) * PS + kc * 4 + tg];
                #pragma unroll
                for (int nt = 0; nt < 4; nt++) {
                    uint2 bv = vp2[(32 * h + 8 * nt + g) * VS + kc * 4 + tg];
                    mma8(oacc[hh][nt], pa.x, pb.x, pa.y, pb.y, bv.x, bv.y);
                }
            }
        }
    }
    __syncthreads();   // all P reads done before O overlays the region

    // store O
    #pragma unroll
    for (int hh = 0; hh < 2; hh++) {
        const int h = hh ? h1 : h0;
        #pragma unroll
        for (int nt = 0; nt < 4; nt++)
            #pragma unroll
            for (int e = 0; e < 4; e++) {
                int row = 16 * mi + g + ((e >= 2) ? 8 : 0);
                int col = 32 * h + 8 * nt + 2 * tg + (e & 1);
                op[rm(row, col)] = f2tf(oacc[hh][nt][e]);
            }
    }
    __syncthreads();

    // ---- Phase 5: out = O @ proj_w + proj_b  (M=16 x N=64 per warp) ----
    {
        int colP[8];
        #pragma unroll
        for (int nt = 0; nt < 8; nt++) colP[nt] = 64 * hp + 8 * nt;
        float acc[8][4];
        gemm16(op2, g_wp, 512, mi, g, tg, colP, acc);

        float* og = out + (size_t)b * NTOK * CDIM;
        #pragma unroll
        for (int nt = 0; nt < 8; nt++) {
            int cc = colP[nt] + 2 * tg;
            float pb0 = __ldg(proj_b + cc);
            float pb1 = __ldg(proj_b + cc + 1);
            int r0 = 16 * mi + g;
            if (r0 < NTOK) {
                float2 v = make_float2(acc[nt][0] + pb0, acc[nt][1] + pb1);
                *(float2*)(og + r0 * CDIM + cc) = v;
            }
            if (r0 + 8 < NTOK) {
                float2 v = make_float2(acc[nt][2] + pb0, acc[nt][3] + pb1);
                *(float2*)(og + (r0 + 8) * CDIM + cc) = v;
            }
        }
    }
}

extern "C" void kernel_launch(void* const* d_in, const int* in_sizes, int n_in,
                              void* d_out, int out_size) {
    const float* x      = (const float*)d_in[0];
    const float* mask   = (const float*)d_in[1];
    const float* qkv_w  = (const float*)d_in[2];
    const float* qkv_b  = (const float*)d_in[3];
    const float* rtbl   = (const float*)d_in[4];
    const float* proj_w = (const float*)d_in[5];
    const float* proj_b = (const float*)d_in[6];
    float* out = (float*)d_out;

    const int B = in_sizes[0] / (NTOK * CDIM);
    prep_kernel<<<64, 512>>>(qkv_w, proj_w);

    const int smem_bytes = SMEM_U32 * sizeof(uint32_t);
    cudaFuncSetAttribute(winattn3_kernel,
                         cudaFuncAttributeMaxDynamicSharedMemorySize, smem_bytes);
    winattn3_kernel<<<B, 256, smem_bytes>>>(x, mask, qkv_b, rtbl, proj_b, out);
}

// round 10
// speedup vs baseline: 2.3168x; 1.0813x over previous
#include <cuda_runtime.h>
#include <cstdint>

// WindowAttention fused v4 (sm_103a).
// 256 threads (8 warps), 1 window/CTA, 2 CTAs/SM (smem 104.9KB).
// Uniform 32x32 warp tiles: warp = (mi2 = wid>>2 in {0,1}, h = wid&3).
// Halves B-weight LDG redundancy (4x->2x) and k/v fragment LDS vs v3.1.
// q stays in registers (shfl transpose acc->A frag). Conflict-free pair strides.

#define NTOK 49
#define CDIM 128

#define RS 68   // row-major pair stride (x / k / O)  : CF
#define VS 36   // v col-major pair stride            : CF
#define PS 28   // P row pair stride                  : CF

#define X_OFF   0        // x: 64*68 pairs = 8704 u32 ; P(14336) & O(8704) overlay
#define K_OFF   8704     // k: 56*68 pairs = 7616 u32
#define V_OFF   16320    // v: 128*36 pairs = 9216 u32
#define TBL_OFF 25536    // 676 floats
#define SMEM_U32 26216   // 104864 bytes

__device__ uint2 g_wq[16 * 384 * 4];   // qkv_w tf32 pairs [kc][col][tg]
__device__ uint2 g_wp[16 * 128 * 4];   // proj_w tf32 pairs [kc][col][tg]

__device__ __forceinline__ uint32_t f2tf(float f) {
    uint32_t u;
    asm("cvt.rna.tf32.f32 %0, %1;" : "=r"(u) : "f"(f));
    return u;
}

__device__ __forceinline__ void mma8(float* d,
                                     uint32_t a0, uint32_t a1, uint32_t a2, uint32_t a3,
                                     uint32_t b0, uint32_t b1) {
    asm volatile(
        "mma.sync.aligned.m16n8k8.row.col.f32.tf32.tf32.f32 "
        "{%0,%1,%2,%3},{%4,%5,%6,%7},{%8,%9},{%0,%1,%2,%3};"
        : "+f"(d[0]), "+f"(d[1]), "+f"(d[2]), "+f"(d[3])
        : "r"(a0), "r"(a1), "r"(a2), "r"(a3), "r"(b0), "r"(b1));
}

__device__ __forceinline__ int rm(int r, int c) {
    return ((r * RS + ((c >> 3) << 2) + (c & 3)) << 1) + ((c >> 2) & 1);
}
__device__ __forceinline__ int vm(int c, int r) {
    return ((c * VS + ((r >> 3) << 2) + (r & 3)) << 1) + ((r >> 2) & 1);
}
__device__ __forceinline__ int pm(int pr, int j) {
    return ((pr * PS + ((j >> 3) << 2) + (j & 3)) << 1) + ((j >> 2) & 1);
}

// ---------------- prep: weights -> tf32 packed pairs ----------------
__global__ void prep_kernel(const float* __restrict__ qkv_w,
                            const float* __restrict__ proj_w) {
    int i = blockIdx.x * blockDim.x + threadIdx.x;
    if (i < 16 * 384 * 4) {
        int kc = i / 1536, rem = i - kc * 1536;
        int col = rem >> 2, tg = rem & 3;
        uint2 p;
        p.x = f2tf(qkv_w[(kc * 8 + tg)     * 384 + col]);
        p.y = f2tf(qkv_w[(kc * 8 + tg + 4) * 384 + col]);
        g_wq[i] = p;
    } else {
        int j = i - 16 * 384 * 4;
        if (j < 16 * 128 * 4) {
            int kc = j >> 9, rem = j & 511;
            int col = rem >> 2, tg = rem & 3;
            uint2 p;
            p.x = f2tf(proj_w[(kc * 8 + tg)     * 128 + col]);
            p.y = f2tf(proj_w[(kc * 8 + tg + 4) * 128 + col]);
            g_wp[j] = p;
        }
    }
}

// 32-row x 32-col GEMM: acc[2][4][4] += A(32xK) * W(Kx32), K = 16 kc chunks.
// A from packed-pair smem (stride RS); W from global pairs (double-buffered).
__device__ __forceinline__ void gemm32(const uint2* __restrict__ ap2,
                                       const uint2* __restrict__ w,
                                       int wstride, int mi2, int g, int tg,
                                       int colbase, float acc[2][4][4]) {
    #pragma unroll
    for (int mt = 0; mt < 2; mt++)
        #pragma unroll
        for (int nt = 0; nt < 4; nt++)
            #pragma unroll
            for (int e = 0; e < 4; e++) acc[mt][nt][e] = 0.0f;

    uint2 Bc[4], Bn[4];
    #pragma unroll
    for (int nt = 0; nt < 4; nt++)
        Bc[nt] = __ldg(w + (colbase + 8 * nt + g) * 4 + tg);

    const int r0 = 32 * mi2 + g;
    #pragma unroll
    for (int kc = 0; kc < 16; kc++) {
        if (kc < 15) {
            const uint2* wn = w + (kc + 1) * wstride;
            #pragma unroll
            for (int nt = 0; nt < 4; nt++)
                Bn[nt] = __ldg(wn + (colbase + 8 * nt + g) * 4 + tg);
        }
        #pragma unroll
        for (int mt = 0; mt < 2; mt++) {
            uint2 a0 = ap2[(r0 + 16 * mt) * RS + kc * 4 + tg];
            uint2 a1 = ap2[(r0 + 16 * mt + 8) * RS + kc * 4 + tg];
            #pragma unroll
            for (int nt = 0; nt < 4; nt++)
                mma8(acc[mt][nt], a0.x, a1.x, a0.y, a1.y, Bc[nt].x, Bc[nt].y);
        }
        #pragma unroll
        for (int nt = 0; nt < 4; nt++) Bc[nt] = Bn[nt];
    }
}

__global__ __launch_bounds__(256, 2)
void winattn4_kernel(const float* __restrict__ x,
                     const float* __restrict__ mask,
                     const float* __restrict__ qkv_b,
                     const float* __restrict__ rel_tbl,
                     const float* __restrict__ proj_b,
                     float*       __restrict__ out)
{
    extern __shared__ uint32_t sm[];
    uint32_t* const xp  = sm + X_OFF;
    uint32_t* const kp  = sm + K_OFF;
    uint32_t* const vp  = sm + V_OFF;
    float*    const tbl = (float*)(sm + TBL_OFF);
    uint32_t* const pp  = sm + X_OFF;   // P overlays x + k
    uint32_t* const op  = sm + X_OFF;   // O overlays P after sync

    const uint2* const xp2 = (const uint2*)xp;
    const uint2* const kp2 = (const uint2*)kp;
    const uint2* const vp2 = (const uint2*)vp;
    const uint2* const pp2 = (const uint2*)pp;
    const uint2* const op2 = (const uint2*)op;

    const int tid  = threadIdx.x;
    const int lane = tid & 31;
    const int wid  = tid >> 5;     // 0..7
    const int h    = wid & 3;      // head / col-group
    const int mi2  = wid >> 2;     // 0..1 : 32-row slice
    const int g    = lane >> 2;
    const int tg   = lane & 3;
    const int b    = blockIdx.x;

    // ---- Phase 0: stage x + bias table ----
    {
        const float* xg = x + (size_t)b * NTOK * CDIM;
        for (int i = tid; i < 64 * 128; i += 256) {
            int r = i >> 7, c = i & 127;
            float v = (r < NTOK) ? __ldg(xg + r * CDIM + c) : 0.0f;
            xp[rm(r, c)] = f2tf(v);
        }
        for (int i = tid; i < 169 * 4; i += 256) tbl[i] = __ldg(rel_tbl + i);
    }
    __syncthreads();

    uint32_t qt[2][4][4];   // q tf32 acc-layout fragments (rows 32*mi2.., head h)

    // ---- Phase 1: qkv in three passes (K, V, Q), each 32x32 per warp ----
    {
        float acc[2][4][4];
        const int colK = 128 + 32 * h;
        const int colV = 256 + 32 * h;
        const int colQ = 32 * h;

        // K pass
        gemm32(xp2, g_wq, 1536, mi2, g, tg, colK, acc);
        #pragma unroll
        for (int mt = 0; mt < 2; mt++)
            #pragma unroll
            for (int nt = 0; nt < 4; nt++)
                #pragma unroll
                for (int e = 0; e < 4; e++) {
                    int row = 32 * mi2 + 16 * mt + g + ((e >= 2) ? 8 : 0);
                    int c   = 32 * h + 8 * nt + 2 * tg + (e & 1);
                    float v = acc[mt][nt][e] + __ldg(qkv_b + 128 + c);
                    if (row < 56) kp[rm(row, c)] = f2tf(v);
                }

        // V pass
        gemm32(xp2, g_wq, 1536, mi2, g, tg, colV, acc);
        #pragma unroll
        for (int mt = 0; mt < 2; mt++)
            #pragma unroll
            for (int nt = 0; nt < 4; nt++)
                #pragma unroll
                for (int e = 0; e < 4; e++) {
                    int row = 32 * mi2 + 16 * mt + g + ((e >= 2) ? 8 : 0);
                    int c   = 32 * h + 8 * nt + 2 * tg + (e & 1);
                    float v = acc[mt][nt][e] + __ldg(qkv_b + 256 + c);
                    if (row < 56) vp[vm(c, row)] = f2tf(v);
                }

        // Q pass -> registers only
        const float scale = 0.17677669529663687f;  // 32^-0.5
        gemm32(xp2, g_wq, 1536, mi2, g, tg, colQ, acc);
        #pragma unroll
        for (int mt = 0; mt < 2; mt++)
            #pragma unroll
            for (int nt = 0; nt < 4; nt++)
                #pragma unroll
                for (int e = 0; e < 4; e++) {
                    int c = 32 * h + 8 * nt + 2 * tg + (e & 1);
                    qt[mt][nt][e] = f2tf((acc[mt][nt][e] + __ldg(qkv_b + c)) * scale);
                }
    }
    __syncthreads();

    // ---- Phase 2: S = q k^T, one head, 32 rows per warp ----
    float sacc[2][7][4];
    {
        const int src0 = (lane & ~3) | (tg >> 1);
        const int src1 = src0 + 2;
        const bool hi  = (tg & 1);
        #pragma unroll
        for (int mt = 0; mt < 2; mt++)
            #pragma unroll
            for (int nt = 0; nt < 7; nt++)
                #pragma unroll
                for (int e = 0; e < 4; e++) sacc[mt][nt][e] = 0.0f;

        #pragma unroll
        for (int kcl = 0; kcl < 4; kcl++) {
            // k fragments for this head-kc chunk, shared across both m-tiles
            uint2 bk[7];
            #pragma unroll
            for (int nt = 0; nt < 7; nt++)
                bk[nt] = kp2[(nt * 8 + g) * RS + (h * 4 + kcl) * 4 + tg];
            #pragma unroll
            for (int mt = 0; mt < 2; mt++) {
                uint32_t u00 = __shfl_sync(0xffffffffu, qt[mt][kcl][0], src0);
                uint32_t u01 = __shfl_sync(0xffffffffu, qt[mt][kcl][1], src0);
                uint32_t u10 = __shfl_sync(0xffffffffu, qt[mt][kcl][2], src0);
                uint32_t u11 = __shfl_sync(0xffffffffu, qt[mt][kcl][3], src0);
                uint32_t v00 = __shfl_sync(0xffffffffu, qt[mt][kcl][0], src1);
                uint32_t v01 = __shfl_sync(0xffffffffu, qt[mt][kcl][1], src1);
                uint32_t v10 = __shfl_sync(0xffffffffu, qt[mt][kcl][2], src1);
                uint32_t v11 = __shfl_sync(0xffffffffu, qt[mt][kcl][3], src1);
                uint32_t a0 = hi ? u01 : u00;
                uint32_t a1 = hi ? u11 : u10;
                uint32_t a2 = hi ? v01 : v00;
                uint32_t a3 = hi ? v11 : v10;
                #pragma unroll
                for (int nt = 0; nt < 7; nt++)
                    mma8(sacc[mt][nt], a0, a1, a2, a3, bk[nt].x, bk[nt].y);
            }
        }
    }
    __syncthreads();   // all k reads done; P may overlay x+k

    // ---- Phase 3: softmax (registers) -> P ----
    {
        const float* mbase = mask + (size_t)b * NTOK * NTOK;
        #pragma unroll
        for (int mt = 0; mt < 2; mt++)
            #pragma unroll
            for (int half = 0; half < 2; half++) {
                int rr = 32 * mi2 + 16 * mt + g + 8 * half;
                bool rv = rr < NTOK;
                int rq = rv ? ((rr * 9363) >> 16) : 0;   // rr/7
                int rmm = rv ? (rr - rq * 7) : 0;

                float vals[14];
                float mx = -1e30f;
                #pragma unroll
                for (int nt = 0; nt < 7; nt++)
                    #pragma unroll
                    for (int e = 0; e < 2; e++) {
                        int j = nt * 8 + 2 * tg + e;
                        float s = sacc[mt][nt][half * 2 + e];
                        if (j < NTOK) {
                            if (rv) {
                                int cq = (j * 9363) >> 16;
                                int cm = j - cq * 7;
                                int rel = (rq - cq + 6) * 13 + (rmm - cm + 6);
                                s += tbl[rel * 4 + h] + __ldg(mbase + rr * NTOK + j);
                            }
                        } else {
                            s = -1e30f;
                        }
                        vals[nt * 2 + e] = s;
                        mx = fmaxf(mx, s);
                    }
                mx = fmaxf(mx, __shfl_xor_sync(0xffffffffu, mx, 1));
                mx = fmaxf(mx, __shfl_xor_sync(0xffffffffu, mx, 2));
                float sum = 0.0f;
                #pragma unroll
                for (int i = 0; i < 14; i++) {
                    vals[i] = __expf(vals[i] - mx);
                    sum += vals[i];
                }
                sum += __shfl_xor_sync(0xffffffffu, sum, 1);
                sum += __shfl_xor_sync(0xffffffffu, sum, 2);
                float inv = 1.0f / sum;
                int pr = h * 64 + rr;
                #pragma unroll
                for (int nt = 0; nt < 7; nt++)
                    #pragma unroll
                    for (int e = 0; e < 2; e++) {
                        int j = nt * 8 + 2 * tg + e;
                        pp[pm(pr, j)] = f2tf(vals[nt * 2 + e] * inv);
                    }
            }
    }
    __syncwarp();   // each warp reads only its own P rows in phase 4

    // ---- Phase 4: O = P @ v, one head, 32 rows per warp ----
    float oacc[2][4][4];
    {
        #pragma unroll
        for (int mt = 0; mt < 2; mt++)
            #pragma unroll
            for (int nt = 0; nt < 4; nt++)
                #pragma unroll
                for (int e = 0; e < 4; e++) oacc[mt][nt][e] = 0.0f;

        #pragma unroll
        for (int kc = 0; kc < 7; kc++) {
            uint2 bv[4];   // v fragments shared across both m-tiles
            #pragma unroll
            for (int nt = 0; nt < 4; nt++)
                bv[nt] = vp2[(32 * h + 8 * nt + g) * VS + kc * 4 + tg];
            #pragma unroll
            for (int mt = 0; mt < 2; mt++) {
                uint2 pa = pp2[(h * 64 + 32 * mi2 + 16 * mt + g) * PS + kc * 4 + tg];
                uint2 pb = pp2[(h * 64 + 32 * mi2 + 16 * mt + 8 + g) * PS + kc * 4 + tg];
                #pragma unroll
                for (int nt = 0; nt < 4; nt++)
                    mma8(oacc[mt][nt], pa.x, pb.x, pa.y, pb.y, bv[nt].x, bv[nt].y);
            }
        }
    }
    __syncthreads();   // all P reads done before O overlays the region

    // store O
    #pragma unroll
    for (int mt = 0; mt < 2; mt++)
        #pragma unroll
        for (int nt = 0; nt < 4; nt++)
            #pragma unroll
            for (int e = 0; e < 4; e++) {
                int row = 32 * mi2 + 16 * mt + g + ((e >= 2) ? 8 : 0);
                int col = 32 * h + 8 * nt + 2 * tg + (e & 1);
                op[rm(row, col)] = f2tf(oacc[mt][nt][e]);
            }
    __syncthreads();

    // ---- Phase 5: out = O @ proj_w + proj_b  (32x32 per warp) ----
    {
        float acc[2][4][4];
        gemm32(op2, g_wp, 512, mi2, g, tg, 32 * h, acc);

        float* og = out + (size_t)b * NTOK * CDIM;
        #pragma unroll
        for (int nt = 0; nt < 4; nt++) {
            int cc = 32 * h + 8 * nt + 2 * tg;
            float pb0 = __ldg(proj_b + cc);
            float pb1 = __ldg(proj_b + cc + 1);
            #pragma unroll
            for (int mt = 0; mt < 2; mt++) {
                int r0 = 32 * mi2 + 16 * mt + g;
                if (r0 < NTOK) {
                    float2 v = make_float2(acc[mt][nt][0] + pb0, acc[mt][nt][1] + pb1);
                    *(float2*)(og + r0 * CDIM + cc) = v;
                }
                if (r0 + 8 < NTOK) {
                    float2 v = make_float2(acc[mt][nt][2] + pb0, acc[mt][nt][3] + pb1);
                    *(float2*)(og + (r0 + 8) * CDIM + cc) = v;
                }
            }
        }
    }
}

extern "C" void kernel_launch(void* const* d_in, const int* in_sizes, int n_in,
                              void* d_out, int out_size) {
    const float* x      = (const float*)d_in[0];
    const float* mask   = (const float*)d_in[1];
    const float* qkv_w  = (const float*)d_in[2];
    const float* qkv_b  = (const float*)d_in[3];
    const float* rtbl   = (const float*)d_in[4];
    const float* proj_w = (const float*)d_in[5];
    const float* proj_b = (const float*)d_in[6];
    float* out = (float*)d_out;

    const int B = in_sizes[0] / (NTOK * CDIM);
    prep_kernel<<<64, 512>>>(qkv_w, proj_w);

    const int smem_bytes = SMEM_U32 * sizeof(uint32_t);
    cudaFuncSetAttribute(winattn4_kernel,
                         cudaFuncAttributeMaxDynamicSharedMemorySize, smem_bytes);
    winattn4_kernel<<<B, 256, smem_bytes>>>(x, mask, qkv_b, rtbl, proj_b, out);
}